// round 14
// baseline (speedup 1.0000x reference)
#include <cuda_runtime.h>
#include <cuda_fp16.h>
#include <cstdint>

#define NN 50000
#define F1 256
#define F2 128
#define ELLW 96

// -------- scratch (static device globals; no allocation) --------
// g_cnt starts zeroed (static init) and is RE-zeroed by the LAST gather each
// call, so every graph replay sees zeros.
__device__ int g_cnt[NN];
__device__ int g_srcs[(size_t)NN * ELLW];
__device__ __align__(16) float  g_dinv[NN];
__device__ __align__(16) __half g_hx [(size_t)NN * F1];   // fp16 x
__device__ __align__(16) __half g_hw1[256 * F1];          // fp16 W1
__device__ __align__(16) __half g_hw2[256 * F2];          // fp16 W2
__device__ __align__(16) __half g_hh1[(size_t)NN * F1];   // fp16 x@W1 (UNSCALED)
__device__ __align__(16) __half g_h1h[(size_t)NN * F1];   // fp16 relu'd layer-1 out
__device__ __align__(16) __half g_hh2[(size_t)NN * F2];   // fp16 (h1@W2)*dinv
// 1 if edge_index is int64; sticky 0 for int32 (same inputs -> same value).
__device__ int g_is64 = 1;

__device__ __forceinline__ uint32_t smem_u32(const void* p) {
    uint32_t a;
    asm("{ .reg .u64 t; cvta.to.shared.u64 t, %1; cvt.u32.u64 %0, t; }" : "=r"(a) : "l"(p));
    return a;
}

#define MMA16816(d, a0, a1, a2, a3, b0, b1)                                   \
    asm volatile(                                                             \
        "mma.sync.aligned.m16n8k16.row.col.f32.f16.f16.f32 "                  \
        "{%0,%1,%2,%3}, {%4,%5,%6,%7}, {%8,%9}, {%0,%1,%2,%3};"               \
        : "+f"((d)[0]), "+f"((d)[1]), "+f"((d)[2]), "+f"((d)[3])              \
        : "r"(a0), "r"(a1), "r"(a2), "r"(a3), "r"(b0), "r"(b1))

#define LDSM_X4(r0, r1, r2, r3, addr)                                         \
    asm volatile("ldmatrix.sync.aligned.m8n8.x4.shared.b16 {%0,%1,%2,%3}, [%4];" \
        : "=r"(r0), "=r"(r1), "=r"(r2), "=r"(r3) : "r"(addr))

#define LDSM_X4_T(r0, r1, r2, r3, addr)                                       \
    asm volatile("ldmatrix.sync.aligned.m8n8.x4.trans.shared.b16 {%0,%1,%2,%3}, [%4];" \
        : "=r"(r0), "=r"(r1), "=r"(r2), "=r"(r3) : "r"(addr))

__device__ __forceinline__ void cvt4(const float4* s, uint2* d, int j) {
    float4 v = s[j];
    __half2 h0 = __floats2half2_rn(v.x, v.y);
    __half2 h1 = __floats2half2_rn(v.z, v.w);
    uint2 o;
    o.x = *(uint32_t*)&h0;
    o.y = *(uint32_t*)&h1;
    d[j] = o;
}

// -------- shared edge helpers (4-edge groups) --------
__device__ __forceinline__ void load_dst4(const int* __restrict__ ew, int E, int e0,
                                          int is64, int cnt, int* d) {
    if (cnt == 4) {
        if (is64) {
            const int4* p = (const int4*)(ew + 2 * (size_t)E + 2 * e0);
            int4 a = p[0], b = p[1];
            d[0] = a.x; d[1] = a.z; d[2] = b.x; d[3] = b.z;
        } else {
            int4 a = *(const int4*)(ew + (size_t)E + e0);
            d[0] = a.x; d[1] = a.y; d[2] = a.z; d[3] = a.w;
        }
    } else {
        for (int j = 0; j < cnt; j++)
            d[j] = is64 ? ew[2 * ((size_t)E + e0 + j)] : ew[(size_t)E + e0 + j];
    }
}
__device__ __forceinline__ void load_src4(const int* __restrict__ ew, int E, int e0,
                                          int is64, int cnt, int* s) {
    if (cnt == 4) {
        if (is64) {
            const int4* p = (const int4*)(ew + 2 * (size_t)e0);
            int4 a = p[0], b = p[1];
            s[0] = a.x; s[1] = a.z; s[2] = b.x; s[3] = b.z;
        } else {
            int4 a = *(const int4*)(ew + e0);
            s[0] = a.x; s[1] = a.y; s[2] = a.z; s[3] = a.w;
        }
    } else {
        for (int j = 0; j < cnt; j++)
            s[j] = is64 ? ew[2 * (size_t)(e0 + j)] : ew[e0 + j];
    }
}

// ======== k_detect: edge dtype sniff (1 block) ========
__global__ void k_detect(const int* __restrict__ w, int nwords) {
    __shared__ int ok;
    if (threadIdx.x == 0) ok = 1;
    __syncthreads();
    for (int i = threadIdx.x; i < nwords / 2; i += blockDim.x)
        if (w[2 * i + 1] != 0) ok = 0;   // benign race
    __syncthreads();
    if (threadIdx.x == 0 && !ok) g_is64 = 0;
}

// ======== k_init: f2h of x, W1, W2 ========
__global__ void k_init(const float4* __restrict__ x, uint2* __restrict__ hx, int nx,
                       const float4* __restrict__ w1, uint2* __restrict__ hw1, int n1,
                       const float4* __restrict__ w2, uint2* __restrict__ hw2, int n2)
{
    int i = blockIdx.x * blockDim.x + threadIdx.x;
    if (i < nx) { cvt4(x, hx, i); return; }
    i -= nx;
    if (i < n1) { cvt4(w1, hw1, i); return; }
    i -= n1;
    if (i < n2) { cvt4(w2, hw2, i); return; }
}

// ======== k_dinv: dinv = rsqrt(cnt + 1) ========
__global__ void k_dinv(const int* __restrict__ cnt, float* __restrict__ dinv) {
    int i = blockIdx.x * blockDim.x + threadIdx.x;
    if (i < NN) dinv[i] = rsqrtf((float)cnt[i] + 1.0f);
}

// ======== fp16 HMMA GEMM: Ch = half((Ah@Bh) [* dinv[row]]),  K=256 ========
// BKT: tail job does the ELL bucket (counting placement): cnt[dst]++ ->
// srcs[dst*ELLW + slot] = src. cnt pre-zeroed (self-cleaning in gather2).
template <bool BKT>
__global__ __launch_bounds__(256, 2) void k_gemm_h(
    const __half* __restrict__ Ah, const __half* __restrict__ Bh,
    const float* __restrict__ dinv, __half* __restrict__ Ch, int M, int N,
    const int* __restrict__ ew, int* __restrict__ cnt, int* __restrict__ srcs, int E)
{
    constexpr int K = 256;
    constexpr int LDA = 40;                 // halfs: 32 + 8 pad (80B stride)
    constexpr int LDB = 136;                // halfs: 128 + 8 pad (272B stride)
    __shared__ __half As[2][128][LDA];
    __shared__ __half Bs[2][32][LDB];

    int tid = threadIdx.x;
    int w = tid >> 5;
    int lane = tid & 31;
    int gid = lane >> 2;
    int tig = lane & 3;
    int warp_m = w >> 2;                    // 0..1
    int warp_n = w & 3;                     // 0..3
    int row0 = blockIdx.y * 128;
    int col0 = blockIdx.x * 128;

    uint32_t asb = smem_u32(&As[0][0][0]);
    uint32_t bsb = smem_u32(&Bs[0][0][0]);

    float acc[4][4][4];
#pragma unroll
    for (int mt = 0; mt < 4; mt++)
#pragma unroll
        for (int nt = 0; nt < 4; nt++)
#pragma unroll
            for (int q = 0; q < 4; q++) acc[mt][nt][q] = 0.f;

    uint4 ra[2], rb[2];

    auto ldregs = [&](int kt) {
#pragma unroll
        for (int i = 0; i < 2; i++) {
            int u = tid + (i << 8);
            int r = u >> 2, c = (u & 3) * 8;
            int grow = row0 + r;
            ra[i] = (grow < M) ? *(const uint4*)(Ah + (size_t)grow * K + kt + c)
                               : make_uint4(0u, 0u, 0u, 0u);
            int k = u >> 4, cb = (u & 15) * 8;
            rb[i] = *(const uint4*)(Bh + (size_t)(kt + k) * N + col0 + cb);
        }
    };
    auto sts = [&](int b) {
#pragma unroll
        for (int i = 0; i < 2; i++) {
            int u = tid + (i << 8);
            *(uint4*)&As[b][u >> 2][(u & 3) * 8] = ra[i];
            *(uint4*)&Bs[b][u >> 4][(u & 15) * 8] = rb[i];
        }
    };
    auto mmabuf = [&](int b) {
#pragma unroll
        for (int k2 = 0; k2 < 32; k2 += 16) {
            uint32_t bf[4][2];
#pragma unroll
            for (int np = 0; np < 2; np++) {
                int brow = k2 + ((lane >> 3) & 1) * 8 + (lane & 7);
                int bcol = warp_n * 32 + np * 16 + (lane >> 4) * 8;
                uint32_t ad = bsb + (uint32_t)(((b << 5) + brow) * LDB + bcol) * 2;
                LDSM_X4_T(bf[np * 2][0], bf[np * 2][1], bf[np * 2 + 1][0], bf[np * 2 + 1][1], ad);
            }
#pragma unroll
            for (int mt = 0; mt < 4; mt++) {
                int arow = warp_m * 64 + mt * 16 + (lane & 15);
                int kc = k2 + (lane >> 4) * 8;
                uint32_t ad = asb + (uint32_t)(((b << 7) + arow) * LDA + kc) * 2;
                uint32_t a0, a1, a2, a3;
                LDSM_X4(a0, a1, a2, a3, ad);
#pragma unroll
                for (int nt = 0; nt < 4; nt++)
                    MMA16816(acc[mt][nt], a0, a1, a2, a3, bf[nt][0], bf[nt][1]);
            }
        }
    };

    ldregs(0);
    sts(0);
    __syncthreads();
#pragma unroll
    for (int ch = 0; ch < K / 32; ch++) {
        if (ch < K / 32 - 1) ldregs((ch + 1) * 32);
        mmabuf(ch & 1);
        if (ch < K / 32 - 1) sts((ch + 1) & 1);
        __syncthreads();
    }

#pragma unroll
    for (int mt = 0; mt < 4; mt++) {
        int r0 = row0 + warp_m * 64 + mt * 16 + gid;
        int r1 = r0 + 8;
        float s0 = dinv ? ((r0 < M) ? dinv[r0] : 0.f) : 1.f;
        float s1 = dinv ? ((r1 < M) ? dinv[r1] : 0.f) : 1.f;
#pragma unroll
        for (int nt = 0; nt < 4; nt++) {
            int c = col0 + warp_n * 32 + nt * 8 + tig * 2;
            if (r0 < M) {
                __half2 h = __floats2half2_rn(acc[mt][nt][0] * s0, acc[mt][nt][1] * s0);
                *(__half2*)(Ch + (size_t)r0 * N + c) = h;
            }
            if (r1 < M) {
                __half2 h = __floats2half2_rn(acc[mt][nt][2] * s1, acc[mt][nt][3] * s1);
                *(__half2*)(Ch + (size_t)r1 * N + c) = h;
            }
        }
    }

    if (BKT) {
        // ELL bucket: this CTA's slice of 4-edge groups
        int nb = gridDim.x * gridDim.y;
        int bid = blockIdx.y * gridDim.x + blockIdx.x;
        int G4 = (E + 3) >> 2;
        int gpc = (G4 + nb - 1) / nb;
        int g0 = bid * gpc;
        int g1 = g0 + gpc; if (g1 > G4) g1 = G4;
        int is64 = g_is64;
        for (int g = g0 + tid; g < g1; g += 256) {
            int e0 = g * 4;
            int n4 = E - e0; n4 = n4 > 4 ? 4 : n4;
            int s[4], d[4];
            load_src4(ew, E, e0, is64, n4, s);
            load_dst4(ew, E, e0, is64, n4, d);
#pragma unroll
            for (int j = 0; j < 4; j++) {
                if (j < n4) {
                    int p = atomicAdd(cnt + d[j], 1);
                    if (p < ELLW) srcs[(size_t)d[j] * ELLW + p] = s[j];
                }
            }
        }
    }
}

// -------- ELL gather-reduce over fp16 features, fp32 accumulate --------
// WSRC: features unscaled -> weight row by dinv[src] (self loop by dinv[node]).
// OUTH: fp16 output. ZERO: zero cnt[node] after use (last consumer).
template <int FH, bool RELU, bool OUTH, bool WSRC, bool ZERO>
__global__ __launch_bounds__(256) void k_gather_ell(
    const int* __restrict__ cnt, const int* __restrict__ srcs,
    const __half* __restrict__ hsh, const float* __restrict__ dinv,
    const float* __restrict__ bias, void* __restrict__ outv, int* __restrict__ cntw)
{
    constexpr int F = 32 * FH;
    int node = (blockIdx.x * blockDim.x + threadIdx.x) >> 5;
    int lane = threadIdx.x & 31;
    if (node >= NN) return;
    const __half* base = hsh + lane * FH;
    const int* row = srcs + (size_t)node * ELLW;

    float acc[FH];
#pragma unroll
    for (int j = 0; j < FH; j++) acc[j] = 0.f;

    auto accum = [&](int s, float wgt) {
        const __half* p = base + (size_t)s * F;
        if (FH == 8) {
            uint4 v = *(const uint4*)p;
            float2 f;
            f = __half22float2(*(__half2*)&v.x);
            if (WSRC) { acc[0] = fmaf(f.x, wgt, acc[0]); acc[1] = fmaf(f.y, wgt, acc[1]); }
            else      { acc[0] += f.x; acc[1] += f.y; }
            f = __half22float2(*(__half2*)&v.y);
            if (WSRC) { acc[2] = fmaf(f.x, wgt, acc[2]); acc[3] = fmaf(f.y, wgt, acc[3]); }
            else      { acc[2] += f.x; acc[3] += f.y; }
            f = __half22float2(*(__half2*)&v.z);
            if (WSRC) { acc[4] = fmaf(f.x, wgt, acc[4]); acc[5] = fmaf(f.y, wgt, acc[5]); }
            else      { acc[4] += f.x; acc[5] += f.y; }
            f = __half22float2(*(__half2*)&v.w);
            if (WSRC) { acc[6] = fmaf(f.x, wgt, acc[6]); acc[7] = fmaf(f.y, wgt, acc[7]); }
            else      { acc[6] += f.x; acc[7] += f.y; }
        } else {
            uint2 v = *(const uint2*)p;
            float2 f;
            f = __half22float2(*(__half2*)&v.x);
            if (WSRC) { acc[0] = fmaf(f.x, wgt, acc[0]); acc[1] = fmaf(f.y, wgt, acc[1]); }
            else      { acc[0] += f.x; acc[1] += f.y; }
            f = __half22float2(*(__half2*)&v.y);
            if (WSRC) { acc[2] = fmaf(f.x, wgt, acc[2]); acc[3] = fmaf(f.y, wgt, acc[3]); }
            else      { acc[2] += f.x; acc[3] += f.y; }
        }
    };

    float sc = dinv[node];
    int end = cnt[node];
    if (end > ELLW) end = ELLW;
    if (ZERO && lane == 0) cntw[node] = 0;         // self-clean for next replay
    accum(node, sc);                               // self loop
    int e = 0;
    for (; e + 4 <= end; e += 4) {
        int s0 = row[e], s1 = row[e + 1], s2 = row[e + 2], s3 = row[e + 3];
        float w0 = 1.f, w1 = 1.f, w2 = 1.f, w3 = 1.f;
        if (WSRC) { w0 = dinv[s0]; w1 = dinv[s1]; w2 = dinv[s2]; w3 = dinv[s3]; }
        accum(s0, w0); accum(s1, w1); accum(s2, w2); accum(s3, w3);
    }
    for (; e < end; e++) {
        int s = row[e];
        accum(s, WSRC ? dinv[s] : 1.f);
    }

    const float* bp = bias + lane * FH;
    float o[FH];
#pragma unroll
    for (int j = 0; j < FH; j += 4) {
        float4 b = *(const float4*)(bp + j);
        o[j + 0] = sc * acc[j + 0] + b.x;
        o[j + 1] = sc * acc[j + 1] + b.y;
        o[j + 2] = sc * acc[j + 2] + b.z;
        o[j + 3] = sc * acc[j + 3] + b.w;
        if (RELU) {
            o[j + 0] = fmaxf(o[j + 0], 0.f); o[j + 1] = fmaxf(o[j + 1], 0.f);
            o[j + 2] = fmaxf(o[j + 2], 0.f); o[j + 3] = fmaxf(o[j + 3], 0.f);
        }
    }
    if (OUTH) {
        __half* dst = (__half*)outv + (size_t)node * F + lane * FH;
#pragma unroll
        for (int j = 0; j < FH; j += 4) {
            __half2 h0 = __floats2half2_rn(o[j + 0], o[j + 1]);
            __half2 h1 = __floats2half2_rn(o[j + 2], o[j + 3]);
            uint2 hp;
            hp.x = *(uint32_t*)&h0;
            hp.y = *(uint32_t*)&h1;
            *(uint2*)(dst + j) = hp;
        }
    } else {
        float* dst = (float*)outv + (size_t)node * F + lane * FH;
#pragma unroll
        for (int j = 0; j < FH; j += 4) {
            float4 v = make_float4(o[j + 0], o[j + 1], o[j + 2], o[j + 3]);
            *(float4*)(dst + j) = v;
        }
    }
}

extern "C" void kernel_launch(void* const* d_in, const int* in_sizes, int n_in,
                              void* d_out, int out_size)
{
    const float* x  = (const float*)d_in[0];
    const int*   ew = (const int*)d_in[1];   // edge words (int32 view)
    const float* W1 = (const float*)d_in[2];
    const float* b1 = (const float*)d_in[3];
    const float* W2 = (const float*)d_in[4];
    const float* b2 = (const float*)d_in[5];
    const int E = in_sizes[1] / 2;
    const int n = NN;

    int *cnt, *srcs;
    float *dinv;
    __half *hx, *hw1, *hw2, *hh1, *h1h, *hh2;
    cudaGetSymbolAddress((void**)&cnt,  g_cnt);
    cudaGetSymbolAddress((void**)&srcs, g_srcs);
    cudaGetSymbolAddress((void**)&dinv, g_dinv);
    cudaGetSymbolAddress((void**)&hx,   g_hx);
    cudaGetSymbolAddress((void**)&hw1,  g_hw1);
    cudaGetSymbolAddress((void**)&hw2,  g_hw2);
    cudaGetSymbolAddress((void**)&hh1,  g_hh1);
    cudaGetSymbolAddress((void**)&h1h,  g_h1h);
    cudaGetSymbolAddress((void**)&hh2,  g_hh2);

    // ---- dtype sniff ----
    k_detect<<<1, 256>>>(ew, 8192);

    // ---- f2h conversions ----
    const int nx = n * F1 / 4, n1 = 256 * F1 / 4, n2 = 256 * F2 / 4;
    k_init<<<(nx + n1 + n2 + 255) / 256, 256>>>(
        (const float4*)x, (uint2*)hx, nx,
        (const float4*)W1, (uint2*)hw1, n1,
        (const float4*)W2, (uint2*)hw2, n2);

    const int MT = (n + 127) / 128;   // 391 row tiles

    // ---- layer 1 GEMM (unscaled) + ELL bucket tail ----
    {
        dim3 grid(F1 / 128, MT);
        k_gemm_h<true><<<grid, 256>>>(hx, hw1, nullptr, hh1, n, F1, ew, cnt, srcs, E);
    }

    // ---- dinv from cnt ----
    k_dinv<<<(n + 255) / 256, 256>>>(cnt, dinv);

    // ---- layer 1 gather (weights dinv[src], outer dinv[node]) ----
    k_gather_ell<8, true, true, true, false><<<(n * 32 + 255) / 256, 256>>>(
        cnt, srcs, hh1, dinv, b1, h1h, nullptr);

    // ---- layer 2 ----
    {
        dim3 grid(F2 / 128, MT);
        k_gemm_h<false><<<grid, 256>>>(h1h, hw2, dinv, hh2, n, F2, nullptr, nullptr, nullptr, 0);
    }
    k_gather_ell<4, false, false, false, true><<<(n * 32 + 255) / 256, 256>>>(
        cnt, srcs, hh2, dinv, b2, d_out, cnt);
}

// round 15
// speedup vs baseline: 1.2752x; 1.2752x over previous
#include <cuda_runtime.h>
#include <cuda_fp16.h>
#include <cstdint>

#define NN 50000
#define F1 256
#define F2 128
#define EMAX 2000000
#define SCAN_B 1024
#define NBLK ((NN + SCAN_B - 1) / SCAN_B)   // 49

// -------- scratch (static device globals; no allocation) --------
// g_deg starts zeroed (static init) and is RE-zeroed by k_scan_fused after use,
// so every graph replay sees zeros without a dedicated zeroing pass.
__device__ int g_deg[NN];
__device__ int g_off[NN + 1];
__device__ int g_cur[NN];
__device__ int g_bsum[NBLK];
__device__ int g_ctr;
__device__ int g_srcs[EMAX];
__device__ __align__(16) float  g_dinv[NN];
__device__ __align__(16) __half g_hx [(size_t)NN * F1];   // fp16 x
__device__ __align__(16) __half g_hw1[256 * F1];          // fp16 W1
__device__ __align__(16) __half g_hw2[256 * F2];          // fp16 W2
__device__ __align__(16) __half g_hh1[(size_t)NN * F1];   // fp16 (x@W1)*dinv
__device__ __align__(16) __half g_h1h[(size_t)NN * F1];   // fp16 relu'd layer-1 out
__device__ __align__(16) __half g_hh2[(size_t)NN * F2];   // fp16 (h1@W2)*dinv
// 1 if edge_index is int64; sticky 0 for int32 (same inputs -> same value).
__device__ int g_is64 = 1;

__device__ __forceinline__ uint32_t smem_u32(const void* p) {
    uint32_t a;
    asm("{ .reg .u64 t; cvta.to.shared.u64 t, %1; cvt.u32.u64 %0, t; }" : "=r"(a) : "l"(p));
    return a;
}

#define MMA16816(d, a0, a1, a2, a3, b0, b1)                                   \
    asm volatile(                                                             \
        "mma.sync.aligned.m16n8k16.row.col.f32.f16.f16.f32 "                  \
        "{%0,%1,%2,%3}, {%4,%5,%6,%7}, {%8,%9}, {%0,%1,%2,%3};"               \
        : "+f"((d)[0]), "+f"((d)[1]), "+f"((d)[2]), "+f"((d)[3])              \
        : "r"(a0), "r"(a1), "r"(a2), "r"(a3), "r"(b0), "r"(b1))

#define LDSM_X4(r0, r1, r2, r3, addr)                                         \
    asm volatile("ldmatrix.sync.aligned.m8n8.x4.shared.b16 {%0,%1,%2,%3}, [%4];" \
        : "=r"(r0), "=r"(r1), "=r"(r2), "=r"(r3) : "r"(addr))

#define LDSM_X4_T(r0, r1, r2, r3, addr)                                       \
    asm volatile("ldmatrix.sync.aligned.m8n8.x4.trans.shared.b16 {%0,%1,%2,%3}, [%4];" \
        : "=r"(r0), "=r"(r1), "=r"(r2), "=r"(r3) : "r"(addr))

__device__ __forceinline__ void cvt4(const float4* s, uint2* d, int j) {
    float4 v = s[j];
    __half2 h0 = __floats2half2_rn(v.x, v.y);
    __half2 h1 = __floats2half2_rn(v.z, v.w);
    uint2 o;
    o.x = *(uint32_t*)&h0;
    o.y = *(uint32_t*)&h1;
    d[j] = o;
}

// -------- shared edge helpers (4-edge groups) --------
__device__ __forceinline__ void load_dst4(const int* __restrict__ ew, int E, int e0,
                                          int is64, int cnt, int* d) {
    if (cnt == 4) {
        if (is64) {
            const int4* p = (const int4*)(ew + 2 * (size_t)E + 2 * e0);
            int4 a = p[0], b = p[1];
            d[0] = a.x; d[1] = a.z; d[2] = b.x; d[3] = b.z;
        } else {
            int4 a = *(const int4*)(ew + (size_t)E + e0);
            d[0] = a.x; d[1] = a.y; d[2] = a.z; d[3] = a.w;
        }
    } else {
        for (int j = 0; j < cnt; j++)
            d[j] = is64 ? ew[2 * ((size_t)E + e0 + j)] : ew[(size_t)E + e0 + j];
    }
}
__device__ __forceinline__ void load_src4(const int* __restrict__ ew, int E, int e0,
                                          int is64, int cnt, int* s) {
    if (cnt == 4) {
        if (is64) {
            const int4* p = (const int4*)(ew + 2 * (size_t)e0);
            int4 a = p[0], b = p[1];
            s[0] = a.x; s[1] = a.z; s[2] = b.x; s[3] = b.z;
        } else {
            int4 a = *(const int4*)(ew + e0);
            s[0] = a.x; s[1] = a.y; s[2] = a.z; s[3] = a.w;
        }
    } else {
        for (int j = 0; j < cnt; j++)
            s[j] = is64 ? ew[2 * (size_t)(e0 + j)] : ew[e0 + j];
    }
}

// ======== k_detect: edge dtype sniff + scan-counter reset (1 block) ========
__global__ void k_detect(const int* __restrict__ w, int nwords) {
    __shared__ int ok;
    if (threadIdx.x == 0) { ok = 1; g_ctr = 0; }
    __syncthreads();
    for (int i = threadIdx.x; i < nwords / 2; i += blockDim.x)
        if (w[2 * i + 1] != 0) ok = 0;   // benign race
    __syncthreads();
    if (threadIdx.x == 0 && !ok) g_is64 = 0;
}

// ======== k_init: f2h x/W1/W2 + edge degree atomics (deg pre-zeroed) ========
__global__ void k_init(const float4* __restrict__ x, uint2* __restrict__ hx, int nx,
                       const float4* __restrict__ w1, uint2* __restrict__ hw1, int n1,
                       const float4* __restrict__ w2, uint2* __restrict__ hw2, int n2,
                       int* __restrict__ deg, const int* __restrict__ ew, int E)
{
    int i = blockIdx.x * blockDim.x + threadIdx.x;
    if (i < nx) { cvt4(x, hx, i); return; }
    i -= nx;
    if (i < n1) { cvt4(w1, hw1, i); return; }
    i -= n1;
    if (i < n2) { cvt4(w2, hw2, i); return; }
    i -= n2;
    int e0 = i * 4;
    if (e0 >= E) return;
    int cnt = E - e0; cnt = cnt > 4 ? 4 : cnt;
    int d[4];
    load_dst4(ew, E, e0, g_is64, cnt, d);
#pragma unroll
    for (int j = 0; j < 4; j++)
        if (j < cnt) atomicAdd(deg + d[j], 1);
}

// ======== fused single-launch exclusive scan + cur + dinv + deg self-zero ====
// 49 blocks, all co-resident (49 <= 148 SMs) -> arrive-counter spin is safe.
__global__ __launch_bounds__(SCAN_B) void k_scan_fused(
    int* __restrict__ deg, int* __restrict__ off, int* __restrict__ cur,
    float* __restrict__ dinv)
{
    __shared__ int sh[SCAN_B];
    __shared__ int bs[64];
    int t = threadIdx.x;
    int b = blockIdx.x;
    int idx = b * SCAN_B + t;
    int v = (idx < NN) ? deg[idx] : 0;
    sh[t] = v;
    __syncthreads();
#pragma unroll
    for (int d = 1; d < SCAN_B; d <<= 1) {
        int u = 0;
        if (t >= d) u = sh[t - d];
        __syncthreads();
        if (t >= d) sh[t] += u;
        __syncthreads();
    }
    int incl = sh[t];
    if (t == SCAN_B - 1) {
        g_bsum[b] = incl;            // block total
        __threadfence();             // publish before arriving
        atomicAdd(&g_ctr, 1);
    }
    if (t == 0) {
        while (atomicAdd(&g_ctr, 0) < NBLK) { }
        __threadfence();
    }
    __syncthreads();
    if (t < NBLK) bs[t] = __ldcg(&g_bsum[t]);   // L1-bypassing read
    __syncthreads();
    int carry = 0;
    for (int j = 0; j < b; j++) carry += bs[j]; // uniform smem reads (broadcast)
    int o = incl - v + carry;
    if (idx < NN) {
        off[idx] = o;
        cur[idx] = o;
        dinv[idx] = rsqrtf((float)v + 1.0f);
        deg[idx] = 0;                            // ready for next replay
    }
    if (b == NBLK - 1 && t == SCAN_B - 1) off[NN] = carry + incl;  // == E
}

// ======== fp16 HMMA GEMM: Ch = half((Ah@Bh) * dinv[row]),  K=256 ========
// BKT: PROLOGUE job — this CTA buckets its slice of edges into srcs (counting
// sort) BEFORE the mainloop, so later-wave CTAs' latency-bound atomic work
// overlaps earlier CTAs' tensor mainloop on the same SM. The first GEMM tile's
// global loads (ldregs) are issued first so they fly during the bucket.
template <bool BKT>
__global__ __launch_bounds__(256, 2) void k_gemm_h(
    const __half* __restrict__ Ah, const __half* __restrict__ Bh,
    const float* __restrict__ dinv, __half* __restrict__ Ch, int M, int N,
    const int* __restrict__ ew, int* __restrict__ cur, int* __restrict__ srcs, int E)
{
    constexpr int K = 256;
    constexpr int LDA = 40;                 // halfs: 32 + 8 pad (80B stride)
    constexpr int LDB = 136;                // halfs: 128 + 8 pad (272B stride)
    __shared__ __half As[2][128][LDA];
    __shared__ __half Bs[2][32][LDB];

    int tid = threadIdx.x;
    int w = tid >> 5;
    int lane = tid & 31;
    int gid = lane >> 2;
    int tig = lane & 3;
    int warp_m = w >> 2;                    // 0..1
    int warp_n = w & 3;                     // 0..3
    int row0 = blockIdx.y * 128;
    int col0 = blockIdx.x * 128;

    uint32_t asb = smem_u32(&As[0][0][0]);
    uint32_t bsb = smem_u32(&Bs[0][0][0]);

    float acc[4][4][4];
#pragma unroll
    for (int mt = 0; mt < 4; mt++)
#pragma unroll
        for (int nt = 0; nt < 4; nt++)
#pragma unroll
            for (int q = 0; q < 4; q++) acc[mt][nt][q] = 0.f;

    uint4 ra[2], rb[2];

    auto ldregs = [&](int kt) {
#pragma unroll
        for (int i = 0; i < 2; i++) {
            int u = tid + (i << 8);
            int r = u >> 2, c = (u & 3) * 8;
            int grow = row0 + r;
            ra[i] = (grow < M) ? *(const uint4*)(Ah + (size_t)grow * K + kt + c)
                               : make_uint4(0u, 0u, 0u, 0u);
            int k = u >> 4, cb = (u & 15) * 8;
            rb[i] = *(const uint4*)(Bh + (size_t)(kt + k) * N + col0 + cb);
        }
    };
    auto sts = [&](int b) {
#pragma unroll
        for (int i = 0; i < 2; i++) {
            int u = tid + (i << 8);
            *(uint4*)&As[b][u >> 2][(u & 3) * 8] = ra[i];
            *(uint4*)&Bs[b][u >> 4][(u & 15) * 8] = rb[i];
        }
    };
    auto mmabuf = [&](int b) {
#pragma unroll
        for (int k2 = 0; k2 < 32; k2 += 16) {
            uint32_t bf[4][2];
#pragma unroll
            for (int np = 0; np < 2; np++) {
                int brow = k2 + ((lane >> 3) & 1) * 8 + (lane & 7);
                int bcol = warp_n * 32 + np * 16 + (lane >> 4) * 8;
                uint32_t ad = bsb + (uint32_t)(((b << 5) + brow) * LDB + bcol) * 2;
                LDSM_X4_T(bf[np * 2][0], bf[np * 2][1], bf[np * 2 + 1][0], bf[np * 2 + 1][1], ad);
            }
#pragma unroll
            for (int mt = 0; mt < 4; mt++) {
                int arow = warp_m * 64 + mt * 16 + (lane & 15);
                int kc = k2 + (lane >> 4) * 8;
                uint32_t ad = asb + (uint32_t)(((b << 7) + arow) * LDA + kc) * 2;
                uint32_t a0, a1, a2, a3;
                LDSM_X4(a0, a1, a2, a3, ad);
#pragma unroll
                for (int nt = 0; nt < 4; nt++)
                    MMA16816(acc[mt][nt], a0, a1, a2, a3, bf[nt][0], bf[nt][1]);
            }
        }
    };

    // issue first tile's global loads, then bucket (loads fly during atomics)
    ldregs(0);
    if (BKT) {
        int nb = gridDim.x * gridDim.y;
        int bid = blockIdx.y * gridDim.x + blockIdx.x;
        int G4 = (E + 3) >> 2;
        int gpc = (G4 + nb - 1) / nb;
        int g0 = bid * gpc;
        int g1 = g0 + gpc; if (g1 > G4) g1 = G4;
        int is64 = g_is64;
        for (int g = g0 + tid; g < g1; g += 256) {
            int e0 = g * 4;
            int cnt = E - e0; cnt = cnt > 4 ? 4 : cnt;
            int s[4], d[4];
            load_src4(ew, E, e0, is64, cnt, s);
            load_dst4(ew, E, e0, is64, cnt, d);
#pragma unroll
            for (int j = 0; j < 4; j++) {
                if (j < cnt) {
                    int p = atomicAdd(cur + d[j], 1);
                    srcs[p] = s[j];
                }
            }
        }
    }
    sts(0);
    __syncthreads();
#pragma unroll
    for (int ch = 0; ch < K / 32; ch++) {
        if (ch < K / 32 - 1) ldregs((ch + 1) * 32);
        mmabuf(ch & 1);
        if (ch < K / 32 - 1) sts((ch + 1) & 1);
        __syncthreads();
    }

#pragma unroll
    for (int mt = 0; mt < 4; mt++) {
        int r0 = row0 + warp_m * 64 + mt * 16 + gid;
        int r1 = r0 + 8;
        float s0 = (r0 < M) ? dinv[r0] : 0.f;
        float s1 = (r1 < M) ? dinv[r1] : 0.f;
#pragma unroll
        for (int nt = 0; nt < 4; nt++) {
            int c = col0 + warp_n * 32 + nt * 8 + tig * 2;
            if (r0 < M) {
                __half2 h = __floats2half2_rn(acc[mt][nt][0] * s0, acc[mt][nt][1] * s0);
                *(__half2*)(Ch + (size_t)r0 * N + c) = h;
            }
            if (r1 < M) {
                __half2 h = __floats2half2_rn(acc[mt][nt][2] * s1, acc[mt][nt][3] * s1);
                *(__half2*)(Ch + (size_t)r1 * N + c) = h;
            }
        }
    }
}

// -------- CSR gather-reduce over fp16 features, fp32 accumulate --------
// OUTH: write fp16 (for layer-1 output feeding GEMM2); else fp32.
template <int FH, bool RELU, bool OUTH>
__global__ __launch_bounds__(256) void k_gather_h(
    const int* __restrict__ off, const int* __restrict__ srcs,
    const __half* __restrict__ hsh, const float* __restrict__ dinv,
    const float* __restrict__ bias, void* __restrict__ outv)
{
    constexpr int F = 32 * FH;
    int node = (blockIdx.x * blockDim.x + threadIdx.x) >> 5;
    int lane = threadIdx.x & 31;
    if (node >= NN) return;
    const __half* base = hsh + lane * FH;

    float acc[FH];
#pragma unroll
    for (int j = 0; j < FH; j++) acc[j] = 0.f;

    auto accum = [&](int s) {
        const __half* p = base + (size_t)s * F;
        if (FH == 8) {
            uint4 v = *(const uint4*)p;
            float2 f;
            f = __half22float2(*(__half2*)&v.x); acc[0] += f.x; acc[1] += f.y;
            f = __half22float2(*(__half2*)&v.y); acc[2] += f.x; acc[3] += f.y;
            f = __half22float2(*(__half2*)&v.z); acc[4] += f.x; acc[5] += f.y;
            f = __half22float2(*(__half2*)&v.w); acc[6] += f.x; acc[7] += f.y;
        } else {
            uint2 v = *(const uint2*)p;
            float2 f;
            f = __half22float2(*(__half2*)&v.x); acc[0] += f.x; acc[1] += f.y;
            f = __half22float2(*(__half2*)&v.y); acc[2] += f.x; acc[3] += f.y;
        }
    };

    accum(node);                                   // self loop
    int e = off[node], end = off[node + 1];
    for (; e + 4 <= end; e += 4) {
        int s0 = srcs[e], s1 = srcs[e + 1], s2 = srcs[e + 2], s3 = srcs[e + 3];
        accum(s0); accum(s1); accum(s2); accum(s3);
    }
    for (; e < end; e++) accum(srcs[e]);

    float sc = dinv[node];
    const float* bp = bias + lane * FH;
    float o[FH];
#pragma unroll
    for (int j = 0; j < FH; j += 4) {
        float4 b = *(const float4*)(bp + j);
        o[j + 0] = sc * acc[j + 0] + b.x;
        o[j + 1] = sc * acc[j + 1] + b.y;
        o[j + 2] = sc * acc[j + 2] + b.z;
        o[j + 3] = sc * acc[j + 3] + b.w;
        if (RELU) {
            o[j + 0] = fmaxf(o[j + 0], 0.f); o[j + 1] = fmaxf(o[j + 1], 0.f);
            o[j + 2] = fmaxf(o[j + 2], 0.f); o[j + 3] = fmaxf(o[j + 3], 0.f);
        }
    }
    if (OUTH) {
        __half* dst = (__half*)outv + (size_t)node * F + lane * FH;
#pragma unroll
        for (int j = 0; j < FH; j += 4) {
            __half2 h0 = __floats2half2_rn(o[j + 0], o[j + 1]);
            __half2 h1 = __floats2half2_rn(o[j + 2], o[j + 3]);
            uint2 hp;
            hp.x = *(uint32_t*)&h0;
            hp.y = *(uint32_t*)&h1;
            *(uint2*)(dst + j) = hp;
        }
    } else {
        float* dst = (float*)outv + (size_t)node * F + lane * FH;
#pragma unroll
        for (int j = 0; j < FH; j += 4) {
            float4 v = make_float4(o[j + 0], o[j + 1], o[j + 2], o[j + 3]);
            *(float4*)(dst + j) = v;
        }
    }
}

extern "C" void kernel_launch(void* const* d_in, const int* in_sizes, int n_in,
                              void* d_out, int out_size)
{
    const float* x  = (const float*)d_in[0];
    const int*   ew = (const int*)d_in[1];   // edge words (int32 view)
    const float* W1 = (const float*)d_in[2];
    const float* b1 = (const float*)d_in[3];
    const float* W2 = (const float*)d_in[4];
    const float* b2 = (const float*)d_in[5];
    const int E = in_sizes[1] / 2;
    const int n = NN;

    int *deg, *off, *cur, *srcs;
    float *dinv;
    __half *hx, *hw1, *hw2, *hh1, *h1h, *hh2;
    cudaGetSymbolAddress((void**)&deg,  g_deg);
    cudaGetSymbolAddress((void**)&off,  g_off);
    cudaGetSymbolAddress((void**)&cur,  g_cur);
    cudaGetSymbolAddress((void**)&srcs, g_srcs);
    cudaGetSymbolAddress((void**)&dinv, g_dinv);
    cudaGetSymbolAddress((void**)&hx,   g_hx);
    cudaGetSymbolAddress((void**)&hw1,  g_hw1);
    cudaGetSymbolAddress((void**)&hw2,  g_hw2);
    cudaGetSymbolAddress((void**)&hh1,  g_hh1);
    cudaGetSymbolAddress((void**)&h1h,  g_h1h);
    cudaGetSymbolAddress((void**)&hh2,  g_hh2);

    // ---- dtype sniff + scan-counter reset (tiny, first) ----
    k_detect<<<1, 256>>>(ew, 8192);

    // ---- fused init: f2h conversions + edge-degree atomics ----
    const int nx = n * F1 / 4, n1 = 256 * F1 / 4, n2 = 256 * F2 / 4;
    const int E4 = (E + 3) / 4;
    const int tot = nx + n1 + n2 + E4;
    k_init<<<(tot + 255) / 256, 256>>>(
        (const float4*)x, (uint2*)hx, nx,
        (const float4*)W1, (uint2*)hw1, n1,
        (const float4*)W2, (uint2*)hw2, n2,
        deg, ew, E);

    // ---- fused scan: off/cur/dinv + deg self-zero ----
    k_scan_fused<<<NBLK, SCAN_B>>>(deg, off, cur, dinv);

    const int MT = (n + 127) / 128;   // 391 row tiles

    // ---- layer 1: GEMM with bucket prologue (hides under tensor waves) ----
    {
        dim3 grid(F1 / 128, MT);
        k_gemm_h<true><<<grid, 256>>>(hx, hw1, dinv, hh1, n, F1, ew, cur, srcs, E);
    }
    k_gather_h<8, true, true><<<(n * 32 + 255) / 256, 256>>>(off, srcs, hh1, dinv, b1, h1h);

    // ---- layer 2 ----
    {
        dim3 grid(F2 / 128, MT);
        k_gemm_h<false><<<grid, 256>>>(h1h, hw2, dinv, hh2, n, F2, nullptr, nullptr, nullptr, 0);
    }
    k_gather_h<4, false, false><<<(n * 32 + 255) / 256, 256>>>(off, srcs, hh2, dinv, b2, d_out);
}

// round 16
// speedup vs baseline: 1.3008x; 1.0201x over previous
#include <cuda_runtime.h>
#include <cuda_fp16.h>
#include <cstdint>

#define NN 50000
#define F1 256
#define F2 128
#define EMAX 2000000
#define SCAN_B 1024
#define NBLK ((NN + SCAN_B - 1) / SCAN_B)   // 49

// -------- scratch (static device globals; no allocation) --------
__device__ int g_deg[NN];
__device__ int g_off[NN + 1];
__device__ int g_cur[NN];
__device__ int g_bsum[NBLK];
__device__ int g_ctr;
__device__ int g_srcs[EMAX];
__device__ __align__(16) float  g_dinv[NN];
__device__ __align__(16) __half g_hx [(size_t)NN * F1];   // fp16 x
__device__ __align__(16) __half g_hw1[256 * F1];          // fp16 W1
__device__ __align__(16) __half g_hw2[256 * F2];          // fp16 W2
__device__ __align__(16) __half g_hh1[(size_t)NN * F1];   // fp16 (x@W1)*dinv
__device__ __align__(16) __half g_h1h[(size_t)NN * F1];   // fp16 relu'd layer-1 out
__device__ __align__(16) __half g_hh2[(size_t)NN * F2];   // fp16 (h1@W2)*dinv
__device__ int g_is64 = 1;   // sticky 0 for int32 (same inputs -> same value)

__device__ __forceinline__ uint32_t smem_u32(const void* p) {
    uint32_t a;
    asm("{ .reg .u64 t; cvta.to.shared.u64 t, %1; cvt.u32.u64 %0, t; }" : "=r"(a) : "l"(p));
    return a;
}

#define MMA16816(d, a0, a1, a2, a3, b0, b1)                                   \
    asm volatile(                                                             \
        "mma.sync.aligned.m16n8k16.row.col.f32.f16.f16.f32 "                  \
        "{%0,%1,%2,%3}, {%4,%5,%6,%7}, {%8,%9}, {%0,%1,%2,%3};"               \
        : "+f"((d)[0]), "+f"((d)[1]), "+f"((d)[2]), "+f"((d)[3])              \
        : "r"(a0), "r"(a1), "r"(a2), "r"(a3), "r"(b0), "r"(b1))

#define LDSM_X4(r0, r1, r2, r3, addr)                                         \
    asm volatile("ldmatrix.sync.aligned.m8n8.x4.shared.b16 {%0,%1,%2,%3}, [%4];" \
        : "=r"(r0), "=r"(r1), "=r"(r2), "=r"(r3) : "r"(addr))

#define LDSM_X4_T(r0, r1, r2, r3, addr)                                       \
    asm volatile("ldmatrix.sync.aligned.m8n8.x4.trans.shared.b16 {%0,%1,%2,%3}, [%4];" \
        : "=r"(r0), "=r"(r1), "=r"(r2), "=r"(r3) : "r"(addr))

#define CP_ASYNC16(dst, src, sz)                                              \
    asm volatile("cp.async.cg.shared.global [%0], [%1], 16, %2;"              \
        :: "r"(dst), "l"(src), "r"(sz))
#define CP_COMMIT() asm volatile("cp.async.commit_group;")
#define CP_WAIT1()  asm volatile("cp.async.wait_group 1;")
#define CP_WAIT0()  asm volatile("cp.async.wait_group 0;")

__device__ __forceinline__ void cvt4(const float4* s, uint2* d, int j) {
    float4 v = s[j];
    __half2 h0 = __floats2half2_rn(v.x, v.y);
    __half2 h1 = __floats2half2_rn(v.z, v.w);
    uint2 o;
    o.x = *(uint32_t*)&h0;
    o.y = *(uint32_t*)&h1;
    d[j] = o;
}

// -------- shared edge helpers (4-edge groups) --------
__device__ __forceinline__ void load_dst4(const int* __restrict__ ew, int E, int e0,
                                          int is64, int cnt, int* d) {
    if (cnt == 4) {
        if (is64) {
            const int4* p = (const int4*)(ew + 2 * (size_t)E + 2 * e0);
            int4 a = p[0], b = p[1];
            d[0] = a.x; d[1] = a.z; d[2] = b.x; d[3] = b.z;
        } else {
            int4 a = *(const int4*)(ew + (size_t)E + e0);
            d[0] = a.x; d[1] = a.y; d[2] = a.z; d[3] = a.w;
        }
    } else {
        for (int j = 0; j < cnt; j++)
            d[j] = is64 ? ew[2 * ((size_t)E + e0 + j)] : ew[(size_t)E + e0 + j];
    }
}
__device__ __forceinline__ void load_src4(const int* __restrict__ ew, int E, int e0,
                                          int is64, int cnt, int* s) {
    if (cnt == 4) {
        if (is64) {
            const int4* p = (const int4*)(ew + 2 * (size_t)e0);
            int4 a = p[0], b = p[1];
            s[0] = a.x; s[1] = a.z; s[2] = b.x; s[3] = b.z;
        } else {
            int4 a = *(const int4*)(ew + e0);
            s[0] = a.x; s[1] = a.y; s[2] = a.z; s[3] = a.w;
        }
    } else {
        for (int j = 0; j < cnt; j++)
            s[j] = is64 ? ew[2 * (size_t)(e0 + j)] : ew[e0 + j];
    }
}

// ======== k_detect: edge dtype sniff + scan-counter reset (1 block) ========
__global__ void k_detect(const int* __restrict__ w, int nwords) {
    __shared__ int ok;
    if (threadIdx.x == 0) { ok = 1; g_ctr = 0; }
    __syncthreads();
    for (int i = threadIdx.x; i < nwords / 2; i += blockDim.x)
        if (w[2 * i + 1] != 0) ok = 0;   // benign race
    __syncthreads();
    if (threadIdx.x == 0 && !ok) g_is64 = 0;
}

// ======== k_init: f2h x/W1/W2 + edge degree atomics (deg pre-zeroed) ========
__global__ void k_init(const float4* __restrict__ x, uint2* __restrict__ hx, int nx,
                       const float4* __restrict__ w1, uint2* __restrict__ hw1, int n1,
                       const float4* __restrict__ w2, uint2* __restrict__ hw2, int n2,
                       int* __restrict__ deg, const int* __restrict__ ew, int E)
{
    int i = blockIdx.x * blockDim.x + threadIdx.x;
    if (i < nx) { cvt4(x, hx, i); return; }
    i -= nx;
    if (i < n1) { cvt4(w1, hw1, i); return; }
    i -= n1;
    if (i < n2) { cvt4(w2, hw2, i); return; }
    i -= n2;
    int e0 = i * 4;
    if (e0 >= E) return;
    int cnt = E - e0; cnt = cnt > 4 ? 4 : cnt;
    int d[4];
    load_dst4(ew, E, e0, g_is64, cnt, d);
#pragma unroll
    for (int j = 0; j < 4; j++)
        if (j < cnt) atomicAdd(deg + d[j], 1);
}

// ======== fused single-launch exclusive scan + cur + dinv + deg self-zero ====
__global__ __launch_bounds__(SCAN_B) void k_scan_fused(
    int* __restrict__ deg, int* __restrict__ off, int* __restrict__ cur,
    float* __restrict__ dinv)
{
    __shared__ int sh[SCAN_B];
    __shared__ int bs[64];
    int t = threadIdx.x;
    int b = blockIdx.x;
    int idx = b * SCAN_B + t;
    int v = (idx < NN) ? deg[idx] : 0;
    sh[t] = v;
    __syncthreads();
#pragma unroll
    for (int d = 1; d < SCAN_B; d <<= 1) {
        int u = 0;
        if (t >= d) u = sh[t - d];
        __syncthreads();
        if (t >= d) sh[t] += u;
        __syncthreads();
    }
    int incl = sh[t];
    if (t == SCAN_B - 1) {
        g_bsum[b] = incl;
        __threadfence();
        atomicAdd(&g_ctr, 1);
    }
    if (t == 0) {
        while (atomicAdd(&g_ctr, 0) < NBLK) { }
        __threadfence();
    }
    __syncthreads();
    if (t < NBLK) bs[t] = __ldcg(&g_bsum[t]);
    __syncthreads();
    int carry = 0;
    for (int j = 0; j < b; j++) carry += bs[j];
    int o = incl - v + carry;
    if (idx < NN) {
        off[idx] = o;
        cur[idx] = o;
        dinv[idx] = rsqrtf((float)v + 1.0f);
        deg[idx] = 0;
    }
    if (b == NBLK - 1 && t == SCAN_B - 1) off[NN] = carry + incl;
}

// ======== fp16 HMMA GEMM (cp.async 3-stage): Ch = half((Ah@Bh)*dinv) ========
// BKT: prologue buckets this CTA's edge slice (CSR fill) while cp.async
// groups for the first two chunks are in flight.
constexpr int LDA = 40;                       // halfs (80B stride)
constexpr int LDB = 136;                      // halfs (272B stride)
constexpr int A_STG = 128 * LDA * 2;          // 10240 B
constexpr int B_STG = 32 * LDB * 2;           // 8704 B
constexpr int STG_BYTES = A_STG + B_STG;      // 18944 B
constexpr int NSTAGE = 3;
constexpr int GEMM_SMEM = NSTAGE * STG_BYTES; // 56832 B

template <bool BKT>
__global__ __launch_bounds__(256, 2) void k_gemm_h(
    const __half* __restrict__ Ah, const __half* __restrict__ Bh,
    const float* __restrict__ dinv, __half* __restrict__ Ch, int M, int N,
    const int* __restrict__ ew, int* __restrict__ cur, int* __restrict__ srcs, int E)
{
    constexpr int K = 256;
    constexpr int NCH = K / 32;               // 8
    extern __shared__ char dsm[];
    uint32_t sbase = smem_u32(dsm);

    int tid = threadIdx.x;
    int w = tid >> 5;
    int lane = tid & 31;
    int gid = lane >> 2;
    int tig = lane & 3;
    int warp_m = w >> 2;                      // 0..1
    int warp_n = w & 3;                       // 0..3
    int row0 = blockIdx.y * 128;
    int col0 = blockIdx.x * 128;

    float acc[4][4][4];
#pragma unroll
    for (int mt = 0; mt < 4; mt++)
#pragma unroll
        for (int nt = 0; nt < 4; nt++)
#pragma unroll
            for (int q = 0; q < 4; q++) acc[mt][nt][q] = 0.f;

    auto issue = [&](int ch, int s) {
        int kt = ch * 32;
        uint32_t abase = sbase + s * STG_BYTES;
        uint32_t bbase = abase + A_STG;
#pragma unroll
        for (int i = 0; i < 2; i++) {
            int u = tid + (i << 8);
            int r = u >> 2, c = (u & 3) * 8;
            int grow = row0 + r;
            int ok = (grow < M);
            const __half* srcA = Ah + (size_t)(ok ? grow : 0) * K + kt + c;
            CP_ASYNC16(abase + (uint32_t)(r * LDA + c) * 2, srcA, ok ? 16 : 0);
            int k = u >> 4, cb = (u & 15) * 8;
            const __half* srcB = Bh + (size_t)(kt + k) * N + col0 + cb;
            CP_ASYNC16(bbase + (uint32_t)(k * LDB + cb) * 2, srcB, 16);
        }
        CP_COMMIT();
    };

    auto mmabuf = [&](int s) {
        uint32_t abase = sbase + s * STG_BYTES;
        uint32_t bbase = abase + A_STG;
#pragma unroll
        for (int k2 = 0; k2 < 32; k2 += 16) {
            uint32_t bf[4][2];
#pragma unroll
            for (int np = 0; np < 2; np++) {
                int brow = k2 + ((lane >> 3) & 1) * 8 + (lane & 7);
                int bcol = warp_n * 32 + np * 16 + (lane >> 4) * 8;
                uint32_t ad = bbase + (uint32_t)(brow * LDB + bcol) * 2;
                LDSM_X4_T(bf[np * 2][0], bf[np * 2][1], bf[np * 2 + 1][0], bf[np * 2 + 1][1], ad);
            }
#pragma unroll
            for (int mt = 0; mt < 4; mt++) {
                int arow = warp_m * 64 + mt * 16 + (lane & 15);
                int kc = k2 + (lane >> 4) * 8;
                uint32_t ad = abase + (uint32_t)(arow * LDA + kc) * 2;
                uint32_t a0, a1, a2, a3;
                LDSM_X4(a0, a1, a2, a3, ad);
#pragma unroll
                for (int nt = 0; nt < 4; nt++)
                    MMA16816(acc[mt][nt], a0, a1, a2, a3, bf[nt][0], bf[nt][1]);
            }
        }
    };

    // prologue: 2 chunks in flight, then bucket while they fly
    issue(0, 0);
    issue(1, 1);
    if (BKT) {
        int nb = gridDim.x * gridDim.y;
        int bid = blockIdx.y * gridDim.x + blockIdx.x;
        int G4 = (E + 3) >> 2;
        int gpc = (G4 + nb - 1) / nb;
        int g0 = bid * gpc;
        int g1 = g0 + gpc; if (g1 > G4) g1 = G4;
        int is64 = g_is64;
        for (int g = g0 + tid; g < g1; g += 256) {
            int e0 = g * 4;
            int cnt = E - e0; cnt = cnt > 4 ? 4 : cnt;
            int s[4], d[4];
            load_src4(ew, E, e0, is64, cnt, s);
            load_dst4(ew, E, e0, is64, cnt, d);
#pragma unroll
            for (int j = 0; j < 4; j++) {
                if (j < cnt) {
                    int p = atomicAdd(cur + d[j], 1);
                    srcs[p] = s[j];
                }
            }
        }
    }

#pragma unroll
    for (int ch = 0; ch < NCH; ch++) {
        if (ch + 2 < NCH) CP_WAIT1(); else CP_WAIT0();
        __syncthreads();
        if (ch + 2 < NCH) issue(ch + 2, (ch + 2) % NSTAGE);
        mmabuf(ch % NSTAGE);
    }

    // epilogue: scale by dinv, store fp16
#pragma unroll
    for (int mt = 0; mt < 4; mt++) {
        int r0 = row0 + warp_m * 64 + mt * 16 + gid;
        int r1 = r0 + 8;
        float s0 = (r0 < M) ? dinv[r0] : 0.f;
        float s1 = (r1 < M) ? dinv[r1] : 0.f;
#pragma unroll
        for (int nt = 0; nt < 4; nt++) {
            int c = col0 + warp_n * 32 + nt * 8 + tig * 2;
            if (r0 < M) {
                __half2 h = __floats2half2_rn(acc[mt][nt][0] * s0, acc[mt][nt][1] * s0);
                *(__half2*)(Ch + (size_t)r0 * N + c) = h;
            }
            if (r1 < M) {
                __half2 h = __floats2half2_rn(acc[mt][nt][2] * s1, acc[mt][nt][3] * s1);
                *(__half2*)(Ch + (size_t)r1 * N + c) = h;
            }
        }
    }
}

// -------- CSR gather-reduce over fp16 features, fp32 accumulate --------
template <int FH, bool RELU, bool OUTH>
__global__ __launch_bounds__(256) void k_gather_h(
    const int* __restrict__ off, const int* __restrict__ srcs,
    const __half* __restrict__ hsh, const float* __restrict__ dinv,
    const float* __restrict__ bias, void* __restrict__ outv)
{
    constexpr int F = 32 * FH;
    int node = (blockIdx.x * blockDim.x + threadIdx.x) >> 5;
    int lane = threadIdx.x & 31;
    if (node >= NN) return;
    const __half* base = hsh + lane * FH;

    float acc[FH];
#pragma unroll
    for (int j = 0; j < FH; j++) acc[j] = 0.f;

    auto accum = [&](int s) {
        const __half* p = base + (size_t)s * F;
        if (FH == 8) {
            uint4 v = *(const uint4*)p;
            float2 f;
            f = __half22float2(*(__half2*)&v.x); acc[0] += f.x; acc[1] += f.y;
            f = __half22float2(*(__half2*)&v.y); acc[2] += f.x; acc[3] += f.y;
            f = __half22float2(*(__half2*)&v.z); acc[4] += f.x; acc[5] += f.y;
            f = __half22float2(*(__half2*)&v.w); acc[6] += f.x; acc[7] += f.y;
        } else {
            uint2 v = *(const uint2*)p;
            float2 f;
            f = __half22float2(*(__half2*)&v.x); acc[0] += f.x; acc[1] += f.y;
            f = __half22float2(*(__half2*)&v.y); acc[2] += f.x; acc[3] += f.y;
        }
    };

    accum(node);                                   // self loop
    int e = off[node], end = off[node + 1];
    for (; e + 4 <= end; e += 4) {
        int s0 = srcs[e], s1 = srcs[e + 1], s2 = srcs[e + 2], s3 = srcs[e + 3];
        accum(s0); accum(s1); accum(s2); accum(s3);
    }
    for (; e < end; e++) accum(srcs[e]);

    float sc = dinv[node];
    const float* bp = bias + lane * FH;
    float o[FH];
#pragma unroll
    for (int j = 0; j < FH; j += 4) {
        float4 b = *(const float4*)(bp + j);
        o[j + 0] = sc * acc[j + 0] + b.x;
        o[j + 1] = sc * acc[j + 1] + b.y;
        o[j + 2] = sc * acc[j + 2] + b.z;
        o[j + 3] = sc * acc[j + 3] + b.w;
        if (RELU) {
            o[j + 0] = fmaxf(o[j + 0], 0.f); o[j + 1] = fmaxf(o[j + 1], 0.f);
            o[j + 2] = fmaxf(o[j + 2], 0.f); o[j + 3] = fmaxf(o[j + 3], 0.f);
        }
    }
    if (OUTH) {
        __half* dst = (__half*)outv + (size_t)node * F + lane * FH;
#pragma unroll
        for (int j = 0; j < FH; j += 4) {
            __half2 h0 = __floats2half2_rn(o[j + 0], o[j + 1]);
            __half2 h1 = __floats2half2_rn(o[j + 2], o[j + 3]);
            uint2 hp;
            hp.x = *(uint32_t*)&h0;
            hp.y = *(uint32_t*)&h1;
            *(uint2*)(dst + j) = hp;
        }
    } else {
        float* dst = (float*)outv + (size_t)node * F + lane * FH;
#pragma unroll
        for (int j = 0; j < FH; j += 4) {
            float4 v = make_float4(o[j + 0], o[j + 1], o[j + 2], o[j + 3]);
            *(float4*)(dst + j) = v;
        }
    }
}

extern "C" void kernel_launch(void* const* d_in, const int* in_sizes, int n_in,
                              void* d_out, int out_size)
{
    const float* x  = (const float*)d_in[0];
    const int*   ew = (const int*)d_in[1];   // edge words (int32 view)
    const float* W1 = (const float*)d_in[2];
    const float* b1 = (const float*)d_in[3];
    const float* W2 = (const float*)d_in[4];
    const float* b2 = (const float*)d_in[5];
    const int E = in_sizes[1] / 2;
    const int n = NN;

    int *deg, *off, *cur, *srcs;
    float *dinv;
    __half *hx, *hw1, *hw2, *hh1, *h1h, *hh2;
    cudaGetSymbolAddress((void**)&deg,  g_deg);
    cudaGetSymbolAddress((void**)&off,  g_off);
    cudaGetSymbolAddress((void**)&cur,  g_cur);
    cudaGetSymbolAddress((void**)&srcs, g_srcs);
    cudaGetSymbolAddress((void**)&dinv, g_dinv);
    cudaGetSymbolAddress((void**)&hx,   g_hx);
    cudaGetSymbolAddress((void**)&hw1,  g_hw1);
    cudaGetSymbolAddress((void**)&hw2,  g_hw2);
    cudaGetSymbolAddress((void**)&hh1,  g_hh1);
    cudaGetSymbolAddress((void**)&h1h,  g_h1h);
    cudaGetSymbolAddress((void**)&hh2,  g_hh2);

    cudaFuncSetAttribute(k_gemm_h<true>,  cudaFuncAttributeMaxDynamicSharedMemorySize, GEMM_SMEM);
    cudaFuncSetAttribute(k_gemm_h<false>, cudaFuncAttributeMaxDynamicSharedMemorySize, GEMM_SMEM);

    // ---- dtype sniff + scan-counter reset ----
    k_detect<<<1, 256>>>(ew, 8192);

    // ---- fused init: f2h conversions + edge-degree atomics ----
    const int nx = n * F1 / 4, n1 = 256 * F1 / 4, n2 = 256 * F2 / 4;
    const int E4 = (E + 3) / 4;
    const int tot = nx + n1 + n2 + E4;
    k_init<<<(tot + 255) / 256, 256>>>(
        (const float4*)x, (uint2*)hx, nx,
        (const float4*)W1, (uint2*)hw1, n1,
        (const float4*)W2, (uint2*)hw2, n2,
        deg, ew, E);

    // ---- fused scan: off/cur/dinv + deg self-zero ----
    k_scan_fused<<<NBLK, SCAN_B>>>(deg, off, cur, dinv);

    const int MT = (n + 127) / 128;   // 391 row tiles

    // ---- layer 1: GEMM (cp.async 3-stage) with bucket prologue ----
    {
        dim3 grid(F1 / 128, MT);
        k_gemm_h<true><<<grid, 256, GEMM_SMEM>>>(hx, hw1, dinv, hh1, n, F1, ew, cur, srcs, E);
    }
    k_gather_h<8, true, true><<<(n * 32 + 255) / 256, 256>>>(off, srcs, hh1, dinv, b1, h1h);

    // ---- layer 2 ----
    {
        dim3 grid(F2 / 128, MT);
        k_gemm_h<false><<<grid, 256, GEMM_SMEM>>>(h1h, hw2, dinv, hh2, n, F2, nullptr, nullptr, nullptr, 0);
    }
    k_gather_h<4, false, false><<<(n * 32 + 255) / 256, 256>>>(off, srcs, hh2, dinv, b2, d_out);
}